// round 5
// baseline (speedup 1.0000x reference)
#include <cuda_runtime.h>
#include <cuda_bf16.h>
#include <cstdint>

// ---------------------------------------------------------------------------
// QKVProjectedLinear, single-launch fused kernel (mma.sync/HMMA path):
//   G_k = (B_k Ws_k^T B_k^T) A_k^T  [64,1024]   (phase-0 CTAs 128..147)
//   t1  = x @ A_all                 [16384,192] (stage 1, bf16 hi/lo x3)
//   out_k = t1_k @ G_k                          (stage 2)
// 512 threads/CTA, 16 warps, 4Mx4N warp grid.
// ---------------------------------------------------------------------------

#define K3 3
#define DL 1024
#define DS 768
#define RK 64
#define NJ 192
#define DOUT 3072
#define NWORK 128
#define NP0 20
#define NTHR 512

// ------------------------- device scratch ----------------------------------
__device__ __align__(16) float g_U[K3*RK*DS];            // B @ Ws^T   [3,64,768]
__device__ __align__(16) float g_Vp[K3*4*RK*RK];         // partial V  [3,4,64,64]
__device__ __align__(16) __nv_bfloat16 g_Ah[DL*NJ];      // A_all hi [1024,192]
__device__ __align__(16) __nv_bfloat16 g_Al[DL*NJ];
__device__ __align__(16) __nv_bfloat16 g_Gh[K3*RK*DL];   // G hi [3,64,1024]
__device__ __align__(16) __nv_bfloat16 g_Gl[K3*RK*DL];
__device__ int c_A, c_U, c_V, c_G;                        // monotonic flags

__device__ __forceinline__ void splitf(float v, __nv_bfloat16& h, __nv_bfloat16& l){
    h = __float2bfloat16(v);
    l = __float2bfloat16(v - __bfloat162float(h));
}
__device__ __forceinline__ uint32_t pack2(__nv_bfloat16 a, __nv_bfloat16 b){
    __nv_bfloat162 t; t.x = a; t.y = b;
    return *reinterpret_cast<uint32_t*>(&t);
}

// ------------------------- sync helpers ------------------------------------
__device__ __forceinline__ void flag_inc(int* f){
    __syncthreads();
    __threadfence();
    if (threadIdx.x == 0)
        asm volatile("red.release.gpu.global.add.s32 [%0], 1;" :: "l"(f) : "memory");
}
__device__ __forceinline__ void flag_wait(int* f, int thr){
    if (threadIdx.x == 0){
        int v;
        do {
            asm volatile("ld.acquire.gpu.global.s32 %0, [%1];" : "=r"(v) : "l"(f));
            if (v < thr) __nanosleep(128);
        } while (v < thr);
    }
    __syncthreads();
}

// ------------------------- cp.async helpers --------------------------------
__device__ __forceinline__ uint32_t smem_u32(const void* p){
    uint32_t a;
    asm("{ .reg .u64 t; cvta.to.shared.u64 t, %1; cvt.u32.u64 %0, t; }" : "=r"(a) : "l"(p));
    return a;
}
__device__ __forceinline__ void cpa16(uint32_t dst, const void* src){
    asm volatile("cp.async.cg.shared.global [%0], [%1], 16;" :: "r"(dst), "l"(src) : "memory");
}
#define CPA_COMMIT() asm volatile("cp.async.commit_group;" ::: "memory")
#define CPA_WAIT(n)  asm volatile("cp.async.wait_group %0;" :: "n"(n) : "memory")

// ------------------------- mma helpers --------------------------------------
__device__ __forceinline__ void ldsm4(uint32_t* r, const void* p){
    uint32_t a = smem_u32(p);
    asm volatile("ldmatrix.sync.aligned.m8n8.x4.shared.b16 {%0,%1,%2,%3}, [%4];"
        : "=r"(r[0]), "=r"(r[1]), "=r"(r[2]), "=r"(r[3]) : "r"(a));
}
__device__ __forceinline__ void ldsm4t(uint32_t* r, const void* p){
    uint32_t a = smem_u32(p);
    asm volatile("ldmatrix.sync.aligned.m8n8.x4.trans.shared.b16 {%0,%1,%2,%3}, [%4];"
        : "=r"(r[0]), "=r"(r[1]), "=r"(r[2]), "=r"(r[3]) : "r"(a));
}
__device__ __forceinline__ void mma_bf16(float* c, const uint32_t* a, const uint32_t* b){
    asm volatile("mma.sync.aligned.m16n8k16.row.col.f32.bf16.bf16.f32 "
        "{%0,%1,%2,%3}, {%4,%5,%6,%7}, {%8,%9}, {%0,%1,%2,%3};"
        : "+f"(c[0]), "+f"(c[1]), "+f"(c[2]), "+f"(c[3])
        : "r"(a[0]), "r"(a[1]), "r"(a[2]), "r"(a[3]), "r"(b[0]), "r"(b[1]));
}

// ------------------------- phase-0 jobs (512 threads) -----------------------
// U[k,r,s] = sum_t B[k,r,t] * W[(k*768+s), t]
__device__ void p0U_job(int k, int s0, char* smem,
                        const float* __restrict__ B, const float* __restrict__ W){
    float* Bt = (float*)smem;          // [64][65]
    float* Wt = Bt + 64*65;            // [32][65]
    int tid = threadIdx.x;
    float acc[4] = {};
    int r0 = tid & 63, sq = (tid >> 6) * 4;
    for (int t0 = 0; t0 < DS; t0 += 64){
        __syncthreads();
        #pragma unroll
        for (int i = 0; i < 8; i++){
            int idx = tid + (i<<9); int r = idx>>6, t = idx&63;
            Bt[r*65 + t] = B[(k*64 + r)*DS + t0 + t];
        }
        #pragma unroll
        for (int i = 0; i < 4; i++){
            int idx = tid + (i<<9); int s = idx>>6, t = idx&63;
            Wt[s*65 + t] = W[(size_t)(k*DS + s0 + s)*DS + t0 + t];
        }
        __syncthreads();
        #pragma unroll 8
        for (int t = 0; t < 64; t++){
            float a0 = Bt[r0*65 + t];
            #pragma unroll
            for (int j = 0; j < 4; j++) acc[j] += a0 * Wt[(sq+j)*65 + t];
        }
    }
    #pragma unroll
    for (int j = 0; j < 4; j++)
        g_U[(k*64 + r0)*DS + s0 + sq + j] = acc[j];
}

// Vp[k,sc,r,q] = sum_{s in chunk sc} U[k,r,s] * B[k,q,s]
__device__ void p0V_job(int k, int sc, char* smem, const float* __restrict__ B){
    float* Us = (float*)smem;          // [64][65]
    float* Bs = Us + 64*65;
    int tid = threadIdx.x;
    float acc[4][2] = {};
    int r0 = (tid & 15)*4, q0 = (tid >> 4)*2;
    for (int si = 0; si < 3; si++){
        int s0 = sc*192 + si*64;
        __syncthreads();
        #pragma unroll
        for (int i = 0; i < 8; i++){
            int idx = tid + (i<<9); int r = idx>>6, s = idx&63;
            Us[r*65 + s] = g_U[(k*64 + r)*DS + s0 + s];
            Bs[r*65 + s] = B[(k*64 + r)*DS + s0 + s];
        }
        __syncthreads();
        #pragma unroll 4
        for (int s = 0; s < 64; s++){
            float a[4], b[2];
            #pragma unroll
            for (int i = 0; i < 4; i++) a[i] = Us[(r0+i)*65 + s];
            #pragma unroll
            for (int j = 0; j < 2; j++) b[j] = Bs[(q0+j)*65 + s];
            #pragma unroll
            for (int i = 0; i < 4; i++)
                #pragma unroll
                for (int j = 0; j < 2; j++) acc[i][j] += a[i]*b[j];
        }
    }
    #pragma unroll
    for (int i = 0; i < 4; i++)
        #pragma unroll
        for (int j = 0; j < 2; j++)
            g_Vp[((k*4 + sc)*64 + r0 + i)*64 + q0 + j] = acc[i][j];
}

// G[k,r,e] = sum_q V[k,r,q] * A[k,e,q]; writes split bf16 directly
__device__ void p0G_job(int k, int e0, char* smem, const float* __restrict__ A){
    float* Vs = (float*)smem;          // [64][68]
    float* As = Vs + 64*68;
    int tid = threadIdx.x;
    __syncthreads();
    #pragma unroll
    for (int i = 0; i < 8; i++){
        int idx = tid + (i<<9); int a = idx>>6, b = idx&63;
        float v = 0.f;
        #pragma unroll
        for (int sc = 0; sc < 4; sc++) v += g_Vp[((k*4 + sc)*64 + a)*64 + b];
        Vs[a*68 + b] = v;
        As[a*68 + b] = A[(size_t)(k*DL + e0 + a)*RK + b];
    }
    __syncthreads();
    int r0 = (tid & 15)*4, ee = (tid >> 4)*2;
    float acc[4][2] = {};
    #pragma unroll 4
    for (int q = 0; q < 64; q++){
        float a[4], b[2];
        #pragma unroll
        for (int i = 0; i < 4; i++) a[i] = Vs[(r0+i)*68 + q];
        #pragma unroll
        for (int j = 0; j < 2; j++) b[j] = As[(ee+j)*68 + q];
        #pragma unroll
        for (int i = 0; i < 4; i++)
            #pragma unroll
            for (int j = 0; j < 2; j++) acc[i][j] += a[i]*b[j];
    }
    #pragma unroll
    for (int i = 0; i < 4; i++)
        #pragma unroll
        for (int j = 0; j < 2; j++){
            __nv_bfloat16 h, l;
            splitf(acc[i][j], h, l);
            size_t dst = (size_t)(k*64 + r0 + i)*DL + e0 + ee + j;
            g_Gh[dst] = h;
            g_Gl[dst] = l;
        }
}

__device__ void phase0(char* smem, const float* __restrict__ W,
                       const float* __restrict__ A, const float* __restrict__ B){
    const int p = blockIdx.x - NWORK;
    const int tid = threadIdx.x;

    // --- splitA: A[k,d,r] -> g_Ah/g_Al [d][k*64+r]
    for (int idx = p*NTHR + tid; idx < K3*DL*RK; idx += NP0*NTHR){
        int k = idx/(DL*RK); int rem = idx%(DL*RK); int d = rem/RK; int r = rem%RK;
        __nv_bfloat16 h, l;
        splitf(A[idx], h, l);
        g_Ah[d*NJ + k*RK + r] = h;
        g_Al[d*NJ + k*RK + r] = l;
    }
    flag_inc(&c_A);

    // --- U: 72 jobs
    for (int j = p; j < 72; j += NP0)
        p0U_job(j/24, (j%24)*32, smem, B, W);
    flag_inc(&c_U);
    flag_wait(&c_U, NP0);

    // --- V: 12 jobs
    if (p < 12){
        p0V_job(p/4, p%4, smem, B);
        flag_inc(&c_V);
    }
    flag_wait(&c_V, 12);

    // --- G: 48 jobs
    for (int j = p; j < 48; j += NP0)
        p0G_job(j/16, (j%16)*64, smem, A);
    flag_inc(&c_G);
}

// ------------------------- worker smem layout -------------------------------
#define XH_OFF 0
#define XL_OFF 18432
#define AOFF(b,hl)  (36864 + (b)*51200 + (hl)*25600)
#define T1H_OFF 0
#define T1L_OFF 51200
#define GOFF(b,hl)  (102400 + (b)*34816 + (hl)*17408)
#define SMEM_BYTES  172032
#define XPITCH 72
#define APITCH 200
#define TPITCH 200
#define GPITCH 136

__device__ __forceinline__ void issueA(uint32_t sbase, int ci, int b){
    const char* sh = (const char*)g_Ah + (size_t)ci*24576;
    const char* sl = (const char*)g_Al + (size_t)ci*24576;
    uint32_t dh = sbase + AOFF(b,0);
    uint32_t dl = sbase + AOFF(b,1);
    int tid = threadIdx.x;
    #pragma unroll
    for (int i = 0; i < 3; i++){
        int j = tid + (i << 9);
        int r = j / 24, c = j % 24;
        cpa16(dh + r*400 + c*16, sh + j*16);
        cpa16(dl + r*400 + c*16, sl + j*16);
    }
}
__device__ __forceinline__ void issueG(uint32_t sbase, int kq, int nt, int b){
    int e0 = nt << 7;
    const char* sh = (const char*)g_Gh;
    const char* sl = (const char*)g_Gl;
    uint32_t dh = sbase + GOFF(b,0);
    uint32_t dl = sbase + GOFF(b,1);
    int tid = threadIdx.x;
    #pragma unroll
    for (int i = 0; i < 2; i++){
        int j = tid + (i << 9);
        int r = j >> 4, c = j & 15;
        size_t so = ((size_t)(kq*64 + r)*DL + e0)*2 + c*16;
        cpa16(dh + r*272 + c*16, sh + so);
        cpa16(dl + r*272 + c*16, sl + so);
    }
}

__global__ __launch_bounds__(NTHR, 1)
void qkv_main(const float* __restrict__ x, const float* __restrict__ W,
              const float* __restrict__ A, const float* __restrict__ B,
              float* __restrict__ out){
    extern __shared__ char smem[];

    if (blockIdx.x >= NWORK){
        phase0(smem, W, A, B);
        return;
    }

    __nv_bfloat16* xh  = (__nv_bfloat16*)(smem + XH_OFF);
    __nv_bfloat16* xl  = (__nv_bfloat16*)(smem + XL_OFF);
    __nv_bfloat16* t1h = (__nv_bfloat16*)(smem + T1H_OFF);
    __nv_bfloat16* t1l = (__nv_bfloat16*)(smem + T1L_OFF);

    const int tid  = threadIdx.x;
    const int warp = tid >> 5, lane = tid & 31;
    const int wm = warp >> 2, wn = warp & 3;       // 4M x 4N warp grid
    const int row0 = blockIdx.x * 128;
    const int lrow = lane & 15;
    const int lcol = (lane >> 4) << 3;
    const uint32_t sbase = smem_u32(smem);

    // ===== stage 1: t1[128,192] = x[128,1024] @ A_all ======================
    float acc[2][6][4];
    #pragma unroll
    for (int i = 0; i < 2; i++)
        #pragma unroll
        for (int j = 0; j < 6; j++)
            #pragma unroll
            for (int q = 0; q < 4; q++) acc[i][j][q] = 0.f;

    // prefetch x chunk 0 into regs (each thread 4 float4)
    float4 xr[4];
    #pragma unroll
    for (int i = 0; i < 4; i++){
        int idx = tid + (i << 9);
        int r = idx >> 4, c4 = idx & 15;
        xr[i] = *(const float4*)(x + (size_t)(row0 + r)*DL + (c4 << 2));
    }

    flag_wait(&c_A, NP0);
    issueA(sbase, 0, 0);
    CPA_COMMIT();

    for (int ci = 0; ci < 16; ci++){
        const int b = ci & 1;
        // split+store current x regs into smem
        #pragma unroll
        for (int i = 0; i < 4; i++){
            int idx = tid + (i << 9);
            int r = idx >> 4, c4 = idx & 15;
            __nv_bfloat16 h0,h1,h2,h3,l0,l1,l2,l3;
            splitf(xr[i].x,h0,l0); splitf(xr[i].y,h1,l1);
            splitf(xr[i].z,h2,l2); splitf(xr[i].w,h3,l3);
            uint2 ph; ph.x = pack2(h0,h1); ph.y = pack2(h2,h3);
            uint2 pl; pl.x = pack2(l0,l1); pl.y = pack2(l2,l3);
            *(uint2*)(xh + r*XPITCH + (c4 << 2)) = ph;
            *(uint2*)(xl + r*XPITCH + (c4 << 2)) = pl;
        }
        if (ci < 15){
            int d0 = (ci + 1) << 6;
            #pragma unroll
            for (int i = 0; i < 4; i++){
                int idx = tid + (i << 9);
                int r = idx >> 4, c4 = idx & 15;
                xr[i] = *(const float4*)(x + (size_t)(row0 + r)*DL + d0 + (c4 << 2));
            }
            issueA(sbase, ci + 1, (ci + 1) & 1);
            CPA_COMMIT();
            CPA_WAIT(1);
        } else {
            CPA_WAIT(0);
        }
        __syncthreads();

        __nv_bfloat16* Ahs = (__nv_bfloat16*)(smem + AOFF(b,0));
        __nv_bfloat16* Als = (__nv_bfloat16*)(smem + AOFF(b,1));
        #pragma unroll
        for (int ks = 0; ks < 4; ks++){
            uint32_t ah[2][4], al[2][4];
            #pragma unroll
            for (int mt = 0; mt < 2; mt++){
                int off = (wm*32 + mt*16 + lrow)*XPITCH + ks*16 + lcol;
                ldsm4(ah[mt], xh + off);
                ldsm4(al[mt], xl + off);
            }
            #pragma unroll
            for (int pp = 0; pp < 3; pp++){
                uint32_t bh[4], bl[4];
                int off = (ks*16 + lrow)*APITCH + wn*48 + pp*16 + lcol;
                ldsm4t(bh, Ahs + off);
                ldsm4t(bl, Als + off);
                #pragma unroll
                for (int mt = 0; mt < 2; mt++){
                    mma_bf16(acc[mt][2*pp],   ah[mt], bh);
                    mma_bf16(acc[mt][2*pp],   ah[mt], bl);
                    mma_bf16(acc[mt][2*pp],   al[mt], bh);
                    mma_bf16(acc[mt][2*pp+1], ah[mt], bh + 2);
                    mma_bf16(acc[mt][2*pp+1], ah[mt], bl + 2);
                    mma_bf16(acc[mt][2*pp+1], al[mt], bh + 2);
                }
            }
        }
        __syncthreads();
    }

    // spill t1 (split hi/lo) to smem
    #pragma unroll
    for (int mt = 0; mt < 2; mt++){
        int r0w = wm*32 + mt*16 + (lane >> 2);
        #pragma unroll
        for (int nt = 0; nt < 6; nt++){
            int c0 = wn*48 + nt*8 + ((lane & 3) << 1);
            __nv_bfloat16 h0,h1,l0,l1;
            splitf(acc[mt][nt][0], h0, l0); splitf(acc[mt][nt][1], h1, l1);
            *(uint32_t*)(t1h + r0w*TPITCH + c0) = pack2(h0,h1);
            *(uint32_t*)(t1l + r0w*TPITCH + c0) = pack2(l0,l1);
            splitf(acc[mt][nt][2], h0, l0); splitf(acc[mt][nt][3], h1, l1);
            *(uint32_t*)(t1h + (r0w+8)*TPITCH + c0) = pack2(h0,h1);
            *(uint32_t*)(t1l + (r0w+8)*TPITCH + c0) = pack2(l0,l1);
        }
    }
    __syncthreads();

    // ===== stage 2: out chunks [128][128] = t1_k @ G_k chunk ===============
    flag_wait(&c_G, NP0);
    issueG(sbase, 0, 0, 0);
    CPA_COMMIT();

    float acc2[2][4][4];
    for (int t = 0; t < 24; t++){
        const int b = t & 1;
        const int kq = t >> 3, nt = t & 7;
        if (t < 23){
            int tn = t + 1;
            issueG(sbase, tn >> 3, tn & 7, tn & 1);
            CPA_COMMIT();
            CPA_WAIT(1);
        } else {
            CPA_WAIT(0);
        }
        __syncthreads();

        #pragma unroll
        for (int i = 0; i < 2; i++)
            #pragma unroll
            for (int j = 0; j < 4; j++)
                #pragma unroll
                for (int q = 0; q < 4; q++) acc2[i][j][q] = 0.f;

        __nv_bfloat16* Ghs = (__nv_bfloat16*)(smem + GOFF(b,0));
        __nv_bfloat16* Gls = (__nv_bfloat16*)(smem + GOFF(b,1));
        #pragma unroll
        for (int ks = 0; ks < 4; ks++){
            uint32_t th[2][4], tl[2][4];
            #pragma unroll
            for (int mt = 0; mt < 2; mt++){
                int off = (wm*32 + mt*16 + lrow)*TPITCH + kq*64 + ks*16 + lcol;
                ldsm4(th[mt], t1h + off);
                ldsm4(tl[mt], t1l + off);
            }
            #pragma unroll
            for (int pp = 0; pp < 2; pp++){
                uint32_t bh[4], bl[4];
                int off = (ks*16 + lrow)*GPITCH + wn*32 + pp*16 + lcol;
                ldsm4t(bh, Ghs + off);
                ldsm4t(bl, Gls + off);
                #pragma unroll
                for (int mt = 0; mt < 2; mt++){
                    mma_bf16(acc2[mt][2*pp],   th[mt], bh);
                    mma_bf16(acc2[mt][2*pp],   th[mt], bl);
                    mma_bf16(acc2[mt][2*pp],   tl[mt], bh);
                    mma_bf16(acc2[mt][2*pp+1], th[mt], bh + 2);
                    mma_bf16(acc2[mt][2*pp+1], th[mt], bl + 2);
                    mma_bf16(acc2[mt][2*pp+1], tl[mt], bh + 2);
                }
            }
        }
        // epilogue: fp32 stores
        int e0 = nt << 7;
        #pragma unroll
        for (int mt = 0; mt < 2; mt++){
            int rr = row0 + wm*32 + mt*16 + (lane >> 2);
            int cb = kq*1024 + e0 + wn*32 + ((lane & 3) << 1);
            #pragma unroll
            for (int ntt = 0; ntt < 4; ntt++){
                float2 v01 = make_float2(acc2[mt][ntt][0], acc2[mt][ntt][1]);
                float2 v23 = make_float2(acc2[mt][ntt][2], acc2[mt][ntt][3]);
                *(float2*)(out + (size_t)rr*DOUT + cb + ntt*8)       = v01;
                *(float2*)(out + (size_t)(rr + 8)*DOUT + cb + ntt*8) = v23;
            }
        }
        __syncthreads();
    }
}

// ------------------------- launch ------------------------------------------
extern "C" void kernel_launch(void* const* d_in, const int* in_sizes, int n_in,
                              void* d_out, int out_size){
    const float* x = (const float*)d_in[0];
    const float* W = (const float*)d_in[1];
    const float* A = (const float*)d_in[2];
    const float* B = (const float*)d_in[3];
    for (int i = 0; i < n_in; i++){
        switch (in_sizes[i]){
            case 16777216: x = (const float*)d_in[i]; break;   // [2,8192,1024]
            case 1769472:  W = (const float*)d_in[i]; break;   // [2304,768]
            case 196608:   A = (const float*)d_in[i]; break;   // [3,1024,64]
            case 147456:   B = (const float*)d_in[i]; break;   // [3,64,768]
            default: break;
        }
    }
    float* out = (float*)d_out;

    cudaFuncSetAttribute(qkv_main, cudaFuncAttributeMaxDynamicSharedMemorySize, SMEM_BYTES);
    qkv_main<<<NWORK + NP0, NTHR, SMEM_BYTES>>>(x, W, A, B, out);
}

// round 7
// speedup vs baseline: 1.2860x; 1.2860x over previous
#include <cuda_runtime.h>
#include <cuda_fp16.h>
#include <cstdint>

// ---------------------------------------------------------------------------
// QKVProjectedLinear, single-launch fused kernel (HMMA fp16 2-product path):
//   G_k = (B_k Ws_k^T B_k^T) A_k^T  [64,1024]   (phase-0 CTAs 128..147)
//   t1  = x @ A_all                 [16384,192] (stage 1: x split fp16 hi/lo,
//                                                A_all single fp16)
//   out_k = t1_k @ G_k              (stage 2: t1 split hi/lo, G single fp16)
// 256 threads/CTA, 8 warps, 4Mx2N warp grid, product-major MMA ordering.
// ---------------------------------------------------------------------------

#define K3 3
#define DL 1024
#define DS 768
#define RK 64
#define NJ 192
#define DOUT 3072
#define NWORK 128
#define NP0 20
#define NTHR 256

// ------------------------- device scratch ----------------------------------
__device__ __align__(16) float g_U[K3*RK*DS];            // B @ Ws^T   [3,64,768]
__device__ __align__(16) float g_Vp[K3*4*RK*RK];         // partial V  [3,4,64,64]
__device__ __align__(16) __half g_Af[DL*NJ];             // A_all fp16 [1024,192]
__device__ __align__(16) __half g_G[K3*RK*DL];           // G fp16 [3,64,1024]
__device__ int c_A, c_U, c_V, c_G;                        // monotonic flags

__device__ __forceinline__ void splith(float v, __half& h, __half& l){
    h = __float2half(v);
    l = __float2half(v - __half2float(h));
}
__device__ __forceinline__ uint32_t pack2h(__half a, __half b){
    __half2 t; t.x = a; t.y = b;
    return *reinterpret_cast<uint32_t*>(&t);
}

// ------------------------- sync helpers ------------------------------------
__device__ __forceinline__ void flag_inc(int* f){
    __syncthreads();
    __threadfence();
    if (threadIdx.x == 0)
        asm volatile("red.release.gpu.global.add.s32 [%0], 1;" :: "l"(f) : "memory");
}
__device__ __forceinline__ void flag_wait(int* f, int thr){
    if (threadIdx.x == 0){
        int v;
        do {
            asm volatile("ld.acquire.gpu.global.s32 %0, [%1];" : "=r"(v) : "l"(f));
            if (v < thr) __nanosleep(128);
        } while (v < thr);
    }
    __syncthreads();
}

// ------------------------- cp.async helpers --------------------------------
__device__ __forceinline__ uint32_t smem_u32(const void* p){
    uint32_t a;
    asm("{ .reg .u64 t; cvta.to.shared.u64 t, %1; cvt.u32.u64 %0, t; }" : "=r"(a) : "l"(p));
    return a;
}
__device__ __forceinline__ void cpa16(uint32_t dst, const void* src){
    asm volatile("cp.async.cg.shared.global [%0], [%1], 16;" :: "r"(dst), "l"(src) : "memory");
}
#define CPA_COMMIT() asm volatile("cp.async.commit_group;" ::: "memory")
#define CPA_WAIT(n)  asm volatile("cp.async.wait_group %0;" :: "n"(n) : "memory")

// ------------------------- mma helpers --------------------------------------
__device__ __forceinline__ void ldsm4(uint32_t* r, const void* p){
    uint32_t a = smem_u32(p);
    asm volatile("ldmatrix.sync.aligned.m8n8.x4.shared.b16 {%0,%1,%2,%3}, [%4];"
        : "=r"(r[0]), "=r"(r[1]), "=r"(r[2]), "=r"(r[3]) : "r"(a));
}
__device__ __forceinline__ void ldsm4t(uint32_t* r, const void* p){
    uint32_t a = smem_u32(p);
    asm volatile("ldmatrix.sync.aligned.m8n8.x4.trans.shared.b16 {%0,%1,%2,%3}, [%4];"
        : "=r"(r[0]), "=r"(r[1]), "=r"(r[2]), "=r"(r[3]) : "r"(a));
}
__device__ __forceinline__ void mma_f16(float* c, const uint32_t* a, const uint32_t* b){
    asm volatile("mma.sync.aligned.m16n8k16.row.col.f32.f16.f16.f32 "
        "{%0,%1,%2,%3}, {%4,%5,%6,%7}, {%8,%9}, {%0,%1,%2,%3};"
        : "+f"(c[0]), "+f"(c[1]), "+f"(c[2]), "+f"(c[3])
        : "r"(a[0]), "r"(a[1]), "r"(a[2]), "r"(a[3]), "r"(b[0]), "r"(b[1]));
}

// ------------------------- phase-0 jobs (256 threads) -----------------------
// U[k,r,s] = sum_t B[k,r,t] * W[(k*768+s), t]
__device__ void p0U_job(int k, int s0, char* smem,
                        const float* __restrict__ B, const float* __restrict__ W){
    float* Bt = (float*)smem;          // [64][65]
    float* Wt = Bt + 64*65;            // [32][65]
    int tid = threadIdx.x;
    float acc[2][4] = {};
    int r0 = (tid & 31)*2, sq = (tid >> 5)*4;
    for (int t0 = 0; t0 < DS; t0 += 64){
        __syncthreads();
        #pragma unroll
        for (int i = 0; i < 16; i++){
            int idx = tid + (i<<8); int r = idx>>6, t = idx&63;
            Bt[r*65 + t] = B[(k*64 + r)*DS + t0 + t];
        }
        #pragma unroll
        for (int i = 0; i < 8; i++){
            int idx = tid + (i<<8); int s = idx>>6, t = idx&63;
            Wt[s*65 + t] = W[(size_t)(k*DS + s0 + s)*DS + t0 + t];
        }
        __syncthreads();
        #pragma unroll 8
        for (int t = 0; t < 64; t++){
            float a0 = Bt[r0*65 + t], a1 = Bt[(r0+1)*65 + t];
            #pragma unroll
            for (int j = 0; j < 4; j++){
                float b = Wt[(sq+j)*65 + t];
                acc[0][j] += a0*b;
                acc[1][j] += a1*b;
            }
        }
    }
    #pragma unroll
    for (int i = 0; i < 2; i++)
        #pragma unroll
        for (int j = 0; j < 4; j++)
            g_U[(k*64 + r0 + i)*DS + s0 + sq + j] = acc[i][j];
}

// Vp[k,sc,r,q] = sum_{s in chunk sc} U[k,r,s] * B[k,q,s]
__device__ void p0V_job(int k, int sc, char* smem, const float* __restrict__ B){
    float* Us = (float*)smem;          // [64][65]
    float* Bs = Us + 64*65;
    int tid = threadIdx.x;
    float acc[4][4] = {};
    int r0 = (tid & 15)*4, q0 = (tid >> 4)*4;
    for (int si = 0; si < 3; si++){
        int s0 = sc*192 + si*64;
        __syncthreads();
        #pragma unroll
        for (int i = 0; i < 16; i++){
            int idx = tid + (i<<8); int r = idx>>6, s = idx&63;
            Us[r*65 + s] = g_U[(k*64 + r)*DS + s0 + s];
            Bs[r*65 + s] = B[(k*64 + r)*DS + s0 + s];
        }
        __syncthreads();
        #pragma unroll 4
        for (int s = 0; s < 64; s++){
            float a[4], b[4];
            #pragma unroll
            for (int i = 0; i < 4; i++){ a[i] = Us[(r0+i)*65 + s]; b[i] = Bs[(q0+i)*65 + s]; }
            #pragma unroll
            for (int i = 0; i < 4; i++)
                #pragma unroll
                for (int j = 0; j < 4; j++) acc[i][j] += a[i]*b[j];
        }
    }
    #pragma unroll
    for (int i = 0; i < 4; i++)
        #pragma unroll
        for (int j = 0; j < 4; j++)
            g_Vp[((k*4 + sc)*64 + r0 + i)*64 + q0 + j] = acc[i][j];
}

// G[k,r,e] = sum_q V[k,r,q] * A[k,e,q]; writes single fp16 directly
__device__ void p0G_job(int k, int e0, char* smem, const float* __restrict__ A){
    float* Vs = (float*)smem;          // [64][68]
    float* As = Vs + 64*68;
    int tid = threadIdx.x;
    __syncthreads();
    #pragma unroll
    for (int i = 0; i < 16; i++){
        int idx = tid + (i<<8); int a = idx>>6, b = idx&63;
        float v = 0.f;
        #pragma unroll
        for (int sc = 0; sc < 4; sc++) v += g_Vp[((k*4 + sc)*64 + a)*64 + b];
        Vs[a*68 + b] = v;
        As[a*68 + b] = A[(size_t)(k*DL + e0 + a)*RK + b];
    }
    __syncthreads();
    int r0 = (tid & 15)*4, ee = (tid >> 4)*4;
    float acc[4][4] = {};
    #pragma unroll 4
    for (int q = 0; q < 64; q++){
        float a[4], b[4];
        #pragma unroll
        for (int i = 0; i < 4; i++){ a[i] = Vs[(r0+i)*68 + q]; b[i] = As[(ee+i)*68 + q]; }
        #pragma unroll
        for (int i = 0; i < 4; i++)
            #pragma unroll
            for (int j = 0; j < 4; j++) acc[i][j] += a[i]*b[j];
    }
    #pragma unroll
    for (int i = 0; i < 4; i++)
        #pragma unroll
        for (int j = 0; j < 4; j++)
            g_G[(size_t)(k*64 + r0 + i)*DL + e0 + ee + j] = __float2half(acc[i][j]);
}

__device__ void phase0(char* smem, const float* __restrict__ W,
                       const float* __restrict__ A, const float* __restrict__ B){
    const int p = blockIdx.x - NWORK;
    const int tid = threadIdx.x;

    // --- A conversion: A[k,d,r] -> g_Af [d][k*64+r], fp16
    for (int idx = p*NTHR + tid; idx < K3*DL*RK; idx += NP0*NTHR){
        int k = idx/(DL*RK); int rem = idx%(DL*RK); int d = rem/RK; int r = rem%RK;
        g_Af[d*NJ + k*RK + r] = __float2half(A[idx]);
    }
    flag_inc(&c_A);

    // --- U: 72 jobs
    for (int j = p; j < 72; j += NP0)
        p0U_job(j/24, (j%24)*32, smem, B, W);
    flag_inc(&c_U);
    flag_wait(&c_U, NP0);

    // --- V: 12 jobs
    if (p < 12){
        p0V_job(p/4, p%4, smem, B);
        flag_inc(&c_V);
    }
    flag_wait(&c_V, 12);

    // --- G: 48 jobs
    for (int j = p; j < 48; j += NP0)
        p0G_job(j/16, (j%16)*64, smem, A);
    flag_inc(&c_G);
}

// ------------------------- worker smem layout -------------------------------
// stage1: xh [128][72]fp16 @0 (18432), xl @18432 (end 36864)
//         A bufs [b] [64][200]fp16 @36864 + b*25600 (end 88064)
// stage2: t1h [128][200]fp16 @0, t1l @51200 (end 102400) (aliases stage1)
//         G bufs [b] [64][136]fp16 @102400 + b*17408 (end 137216)
#define XH_OFF 0
#define XL_OFF 18432
#define AOFF(b)  (36864 + (b)*25600)
#define T1H_OFF 0
#define T1L_OFF 51200
#define GOFF(b)  (102400 + (b)*17408)
#define SMEM_BYTES  137216
#define XPITCH 72
#define APITCH 200
#define TPITCH 200
#define GPITCH 136

__device__ __forceinline__ void issueA(uint32_t sbase, int ci, int b){
    const char* s = (const char*)g_Af + (size_t)ci*24576;
    uint32_t d = sbase + AOFF(b);
    int tid = threadIdx.x;
    #pragma unroll
    for (int i = 0; i < 6; i++){
        int j = tid + (i << 8);
        int r = j / 24, c = j % 24;
        cpa16(d + r*400 + c*16, s + j*16);
    }
}
__device__ __forceinline__ void issueG(uint32_t sbase, int kq, int nt, int b){
    int e0 = nt << 7;
    uint32_t d = sbase + GOFF(b);
    int tid = threadIdx.x;
    #pragma unroll
    for (int i = 0; i < 4; i++){
        int j = tid + (i << 8);
        int r = j >> 4, c = j & 15;
        cpa16(d + r*272 + c*16, (const char*)g_G + ((size_t)(kq*64 + r)*DL + e0)*2 + c*16);
    }
}

__global__ __launch_bounds__(NTHR, 1)
void qkv_main(const float* __restrict__ x, const float* __restrict__ W,
              const float* __restrict__ A, const float* __restrict__ B,
              float* __restrict__ out){
    extern __shared__ char smem[];

    if (blockIdx.x >= NWORK){
        phase0(smem, W, A, B);
        return;
    }

    __half* xh  = (__half*)(smem + XH_OFF);
    __half* xl  = (__half*)(smem + XL_OFF);
    __half* t1h = (__half*)(smem + T1H_OFF);
    __half* t1l = (__half*)(smem + T1L_OFF);

    const int tid  = threadIdx.x;
    const int warp = tid >> 5, lane = tid & 31;
    const int wm = warp >> 1, wn = warp & 1;       // 4M x 2N warp grid
    const int row0 = blockIdx.x * 128;
    const int lrow = lane & 15;
    const int lcol = (lane >> 4) << 3;
    const uint32_t sbase = smem_u32(smem);

    // ===== stage 1: t1[128,192] = x[128,1024] @ A_all ======================
    float acc[2][12][4];
    #pragma unroll
    for (int i = 0; i < 2; i++)
        #pragma unroll
        for (int j = 0; j < 12; j++)
            #pragma unroll
            for (int q = 0; q < 4; q++) acc[i][j][q] = 0.f;

    // prefetch x chunk 0 into regs
    float4 xr[8];
    #pragma unroll
    for (int i = 0; i < 8; i++){
        int idx = tid + (i << 8);
        int r = idx >> 4, c4 = idx & 15;
        xr[i] = *(const float4*)(x + (size_t)(row0 + r)*DL + (c4 << 2));
    }

    flag_wait(&c_A, NP0);
    issueA(sbase, 0, 0);
    CPA_COMMIT();

    for (int ci = 0; ci < 16; ci++){
        const int b = ci & 1;
        // split+store current x regs into smem (fp16 hi/lo)
        #pragma unroll
        for (int i = 0; i < 8; i++){
            int idx = tid + (i << 8);
            int r = idx >> 4, c4 = idx & 15;
            __half h0,h1,h2,h3,l0,l1,l2,l3;
            splith(xr[i].x,h0,l0); splith(xr[i].y,h1,l1);
            splith(xr[i].z,h2,l2); splith(xr[i].w,h3,l3);
            uint2 ph; ph.x = pack2h(h0,h1); ph.y = pack2h(h2,h3);
            uint2 pl; pl.x = pack2h(l0,l1); pl.y = pack2h(l2,l3);
            *(uint2*)(xh + r*XPITCH + (c4 << 2)) = ph;
            *(uint2*)(xl + r*XPITCH + (c4 << 2)) = pl;
        }
        if (ci < 15){
            int d0 = (ci + 1) << 6;
            #pragma unroll
            for (int i = 0; i < 8; i++){
                int idx = tid + (i << 8);
                int r = idx >> 4, c4 = idx & 15;
                xr[i] = *(const float4*)(x + (size_t)(row0 + r)*DL + d0 + (c4 << 2));
            }
            issueA(sbase, ci + 1, (ci + 1) & 1);
            CPA_COMMIT();
            CPA_WAIT(1);
        } else {
            CPA_WAIT(0);
        }
        __syncthreads();

        __half* As = (__half*)(smem + AOFF(b));
        #pragma unroll
        for (int ks = 0; ks < 4; ks++){
            // load ALL fragments upfront
            uint32_t ah[2][4], al[2][4];
            #pragma unroll
            for (int mt = 0; mt < 2; mt++){
                int off = (wm*32 + mt*16 + lrow)*XPITCH + ks*16 + lcol;
                ldsm4(ah[mt], xh + off);
                ldsm4(al[mt], xl + off);
            }
            uint32_t g[6][4];
            #pragma unroll
            for (int pp = 0; pp < 6; pp++){
                int off = (ks*16 + lrow)*APITCH + wn*96 + pp*16 + lcol;
                ldsm4t(g[pp], As + off);
            }
            // product-major: hi sweep (24 distinct accs), then lo sweep
            #pragma unroll
            for (int pp = 0; pp < 6; pp++)
                #pragma unroll
                for (int mt = 0; mt < 2; mt++){
                    mma_f16(acc[mt][2*pp],   ah[mt], g[pp]);
                    mma_f16(acc[mt][2*pp+1], ah[mt], g[pp] + 2);
                }
            #pragma unroll
            for (int pp = 0; pp < 6; pp++)
                #pragma unroll
                for (int mt = 0; mt < 2; mt++){
                    mma_f16(acc[mt][2*pp],   al[mt], g[pp]);
                    mma_f16(acc[mt][2*pp+1], al[mt], g[pp] + 2);
                }
        }
        __syncthreads();
    }

    // spill t1 (split fp16 hi/lo) to smem
    #pragma unroll
    for (int mt = 0; mt < 2; mt++){
        int r0w = wm*32 + mt*16 + (lane >> 2);
        #pragma unroll
        for (int nt = 0; nt < 12; nt++){
            int c0 = wn*96 + nt*8 + ((lane & 3) << 1);
            __half h0,h1,l0,l1;
            splith(acc[mt][nt][0], h0, l0); splith(acc[mt][nt][1], h1, l1);
            *(uint32_t*)(t1h + r0w*TPITCH + c0) = pack2h(h0,h1);
            *(uint32_t*)(t1l + r0w*TPITCH + c0) = pack2h(l0,l1);
            splith(acc[mt][nt][2], h0, l0); splith(acc[mt][nt][3], h1, l1);
            *(uint32_t*)(t1h + (r0w+8)*TPITCH + c0) = pack2h(h0,h1);
            *(uint32_t*)(t1l + (r0w+8)*TPITCH + c0) = pack2h(l0,l1);
        }
    }
    __syncthreads();

    // ===== stage 2: out chunks [128][128] = t1_k @ G_k chunk ===============
    flag_wait(&c_G, NP0);
    issueG(sbase, 0, 0, 0);
    CPA_COMMIT();

    float acc2[2][8][4];
    for (int t = 0; t < 24; t++){
        const int b = t & 1;
        const int kq = t >> 3, nt = t & 7;
        if (t < 23){
            int tn = t + 1;
            issueG(sbase, tn >> 3, tn & 7, tn & 1);
            CPA_COMMIT();
            CPA_WAIT(1);
        } else {
            CPA_WAIT(0);
        }
        __syncthreads();

        #pragma unroll
        for (int i = 0; i < 2; i++)
            #pragma unroll
            for (int j = 0; j < 8; j++)
                #pragma unroll
                for (int q = 0; q < 4; q++) acc2[i][j][q] = 0.f;

        __half* Gs = (__half*)(smem + GOFF(b));
        #pragma unroll
        for (int ks = 0; ks < 4; ks++){
            uint32_t th[2][4], tl[2][4];
            #pragma unroll
            for (int mt = 0; mt < 2; mt++){
                int off = (wm*32 + mt*16 + lrow)*TPITCH + kq*64 + ks*16 + lcol;
                ldsm4(th[mt], t1h + off);
                ldsm4(tl[mt], t1l + off);
            }
            uint32_t g2[4][4];
            #pragma unroll
            for (int pp = 0; pp < 4; pp++){
                int off = (ks*16 + lrow)*GPITCH + wn*64 + pp*16 + lcol;
                ldsm4t(g2[pp], Gs + off);
            }
            // product-major: hi sweep (16 distinct accs), then lo sweep
            #pragma unroll
            for (int pp = 0; pp < 4; pp++)
                #pragma unroll
                for (int mt = 0; mt < 2; mt++){
                    mma_f16(acc2[mt][2*pp],   th[mt], g2[pp]);
                    mma_f16(acc2[mt][2*pp+1], th[mt], g2[pp] + 2);
                }
            #pragma unroll
            for (int pp = 0; pp < 4; pp++)
                #pragma unroll
                for (int mt = 0; mt < 2; mt++){
                    mma_f16(acc2[mt][2*pp],   tl[mt], g2[pp]);
                    mma_f16(acc2[mt][2*pp+1], tl[mt], g2[pp] + 2);
                }
        }
        // epilogue: fp32 stores
        int e0 = nt << 7;
        #pragma unroll
        for (int mt = 0; mt < 2; mt++){
            int rr = row0 + wm*32 + mt*16 + (lane >> 2);
            int cb = kq*1024 + e0 + wn*64 + ((lane & 3) << 1);
            #pragma unroll
            for (int ntt = 0; ntt < 8; ntt++){
                float2 v01 = make_float2(acc2[mt][ntt][0], acc2[mt][ntt][1]);
                float2 v23 = make_float2(acc2[mt][ntt][2], acc2[mt][ntt][3]);
                *(float2*)(out + (size_t)rr*DOUT + cb + ntt*8)       = v01;
                *(float2*)(out + (size_t)(rr + 8)*DOUT + cb + ntt*8) = v23;
            }
        }
        __syncthreads();
    }
}

// ------------------------- launch ------------------------------------------
extern "C" void kernel_launch(void* const* d_in, const int* in_sizes, int n_in,
                              void* d_out, int out_size){
    const float* x = (const float*)d_in[0];
    const float* W = (const float*)d_in[1];
    const float* A = (const float*)d_in[2];
    const float* B = (const float*)d_in[3];
    for (int i = 0; i < n_in; i++){
        switch (in_sizes[i]){
            case 16777216: x = (const float*)d_in[i]; break;   // [2,8192,1024]
            case 1769472:  W = (const float*)d_in[i]; break;   // [2304,768]
            case 196608:   A = (const float*)d_in[i]; break;   // [3,1024,64]
            case 147456:   B = (const float*)d_in[i]; break;   // [3,64,768]
            default: break;
        }
    }
    float* out = (float*)d_out;

    cudaFuncSetAttribute(qkv_main, cudaFuncAttributeMaxDynamicSharedMemorySize, SMEM_BYTES);
    qkv_main<<<NWORK + NP0, NTHR, SMEM_BYTES>>>(x, W, A, B, out);
}